// round 2
// baseline (speedup 1.0000x reference)
#include <cuda_runtime.h>
#include <math.h>

#define BB    32
#define NN    4096
#define NPQ   512
#define NSAMP 16
#define CC    256
#define HIDC  128
#define NPIX  (BB*NPQ*NSAMP)   /* 262144 */
#define NPTS  (BB*NN)          /* 131072 */

#define OUT_XYZ  0
#define OUT_FEAT (BB*NPQ*3)                  /* 49152 */
#define OUT_INDS (OUT_FEAT + BB*HIDC*NPQ)    /* 2146304 */

// ------------- static scratch (no allocations) -------------
__device__ float  g_PF[(size_t)NPTS*HIDC];    // per-point conv1 feature part (64MB)
__device__ float  g_Y1[(size_t)NPIX*HIDC];    // activations ping (128MB)
__device__ float  g_Y2[(size_t)NPIX*HIDC];    // activations pong (128MB)
__device__ int    g_idx[NPIX];                // ball-query point indices
__device__ float  g_gxyz[(size_t)NPIX*3];     // normalized grouped xyz
__device__ double g_stats[3*2*HIDC];          // per layer: sum[128], sumsq[128]
__device__ float  g_bn[3*3*HIDC];             // per layer: mean[128], scale[128], beta[128]

// ---------------------------------------------------------------------------
__global__ void zero_stats_kernel() {
    int i = blockIdx.x*256 + threadIdx.x;
    if (i < 3*2*HIDC) g_stats[i] = 0.0;
}

// ---------------------------------------------------------------------------
// FPS: one block per batch, 1024 threads, 4 points each.
// Bit-exact distance: ((dx*dx + dy*dy) + dz*dz) with rn ops (no FMA).
__global__ __launch_bounds__(1024) void fps_kernel(
    const float* __restrict__ seed, const float* __restrict__ xyz,
    float* __restrict__ out)
{
    int b = blockIdx.x;
    int t = threadIdx.x;
    int lane = t & 31, wid = t >> 5;
    __shared__ float s_last[3];
    __shared__ float s_rv[32];
    __shared__ int   s_ri[32];
    __shared__ int   s_bi;
    __shared__ int   s_inds[NPQ];

    const float* sb = seed + (size_t)b*NN*3;
    float px[4], py[4], pz[4], dist[4];
#pragma unroll
    for (int j = 0; j < 4; j++) {
        int i = t + j*1024;
        px[j] = sb[i*3+0];
        py[j] = sb[i*3+1];
        pz[j] = sb[i*3+2];
        dist[j] = 1e10f;
    }
    if (t == 0) s_inds[0] = 0;
    int last = 0;

    for (int it = 1; it < NPQ; ++it) {
        if (t == 0) {
            s_last[0] = sb[last*3+0];
            s_last[1] = sb[last*3+1];
            s_last[2] = sb[last*3+2];
        }
        __syncthreads();
        float lx = s_last[0], ly = s_last[1], lz = s_last[2];
        float bv = -1.0f; int bi = 0;
#pragma unroll
        for (int j = 0; j < 4; j++) {
            float dx = __fadd_rn(px[j], -lx);
            float dy = __fadd_rn(py[j], -ly);
            float dz = __fadd_rn(pz[j], -lz);
            float d  = __fadd_rn(__fadd_rn(__fmul_rn(dx,dx), __fmul_rn(dy,dy)),
                                 __fmul_rn(dz,dz));
            dist[j] = fminf(dist[j], d);
            int i = t + j*1024;   // ascending in j -> strict > keeps first index
            if (dist[j] > bv) { bv = dist[j]; bi = i; }
        }
        // warp reduce (max value, smallest index on ties)
#pragma unroll
        for (int off = 16; off > 0; off >>= 1) {
            float ov = __shfl_down_sync(0xffffffffu, bv, off);
            int   oi = __shfl_down_sync(0xffffffffu, bi, off);
            if (ov > bv || (ov == bv && oi < bi)) { bv = ov; bi = oi; }
        }
        if (lane == 0) { s_rv[wid] = bv; s_ri[wid] = bi; }
        __syncthreads();
        if (wid == 0) {
            bv = s_rv[lane]; bi = s_ri[lane];
#pragma unroll
            for (int off = 16; off > 0; off >>= 1) {
                float ov = __shfl_down_sync(0xffffffffu, bv, off);
                int   oi = __shfl_down_sync(0xffffffffu, bi, off);
                if (ov > bv || (ov == bv && oi < bi)) { bv = ov; bi = oi; }
            }
            if (lane == 0) { s_bi = bi; s_inds[it] = bi; }
        }
        __syncthreads();
        last = s_bi;
    }

    // write sample_inds (as float) + new_xyz (gathered from xyz)
    for (int i = t; i < NPQ; i += 1024) {
        int id = s_inds[i];
        out[OUT_INDS + b*NPQ + i] = (float)id;
        const float* xb = xyz + ((size_t)b*NN + id)*3;
        out[((size_t)b*NPQ + i)*3 + 0] = xb[0];
        out[((size_t)b*NPQ + i)*3 + 1] = xb[1];
        out[((size_t)b*NPQ + i)*3 + 2] = xb[2];
    }
}

// ---------------------------------------------------------------------------
// Ball query: one warp per query. First-16-in-index-order semantics via ballot.
__global__ __launch_bounds__(256) void bq_kernel(
    const float* __restrict__ xyz, const float* __restrict__ out)
{
    int q = blockIdx.x*8 + (threadIdx.x >> 5);
    int lane = threadIdx.x & 31;
    int b = q >> 9;
    const float R2c = (float)(0.3*0.3);   // matches python 0.3*0.3 -> f32
    const float RAD = 0.3f;

    float qx = out[(size_t)q*3+0];
    float qy = out[(size_t)q*3+1];
    float qz = out[(size_t)q*3+2];
    const float* xb = xyz + (size_t)b*NN*3;

    int found = 0, firstIdx = -1;
    for (int s = 0; s < NN/32 && found < NSAMP; ++s) {
        int i = s*32 + lane;
        float x = xb[i*3+0], y = xb[i*3+1], z = xb[i*3+2];
        float dx = __fadd_rn(qx, -x);
        float dy = __fadd_rn(qy, -y);
        float dz = __fadd_rn(qz, -z);
        float d  = __fadd_rn(__fadd_rn(__fmul_rn(dx,dx), __fmul_rn(dy,dy)),
                             __fmul_rn(dz,dz));
        bool pred = d < R2c;
        unsigned mask = __ballot_sync(0xffffffffu, pred);
        if (firstIdx < 0 && mask) {
            int src = __ffs(mask) - 1;
            firstIdx = s*32 + src;
        }
        if (pred) {
            int rank = __popc(mask & ((1u << lane) - 1u));
            int pos = found + rank;
            if (pos < NSAMP) {
                g_idx[q*NSAMP + pos] = i;
                g_gxyz[((size_t)q*NSAMP + pos)*3 + 0] = __fdiv_rn(__fadd_rn(x, -qx), RAD);
                g_gxyz[((size_t)q*NSAMP + pos)*3 + 1] = __fdiv_rn(__fadd_rn(y, -qy), RAD);
                g_gxyz[((size_t)q*NSAMP + pos)*3 + 2] = __fdiv_rn(__fadd_rn(z, -qz), RAD);
            }
        }
        found += __popc(mask);
    }
    if (found < NSAMP) {
        // pad with first hit (always exists: query point itself has d=0)
        float fx = xb[firstIdx*3+0], fy = xb[firstIdx*3+1], fz = xb[firstIdx*3+2];
        float g0 = __fdiv_rn(__fadd_rn(fx, -qx), RAD);
        float g1 = __fdiv_rn(__fadd_rn(fy, -qy), RAD);
        float g2 = __fdiv_rn(__fadd_rn(fz, -qz), RAD);
        if (lane >= found && lane < NSAMP) {
            g_idx[q*NSAMP + lane] = firstIdx;
            g_gxyz[((size_t)q*NSAMP + lane)*3 + 0] = g0;
            g_gxyz[((size_t)q*NSAMP + lane)*3 + 1] = g1;
            g_gxyz[((size_t)q*NSAMP + lane)*3 + 2] = g2;
        }
    }
}

// ---------------------------------------------------------------------------
// GEMM1: PF[b,m,o] = sum_c features[b,c,m] * w1[o, 3+c]
// per batch: M=4096, N=128, K=256. 128x128 tile, BK=16, 256 thr, 8x8 micro.
__global__ __launch_bounds__(256) void gemm1_kernel(
    const float* __restrict__ feat, const float* __restrict__ w1)
{
    __shared__ float As[16*128];
    __shared__ float Bs[16*128];
    int b = blockIdx.z;
    int mBase = blockIdx.x*128;
    const float* A = feat + (size_t)b*CC*NN;
    float* C = g_PF + ((size_t)b*NN + mBase)*HIDC;
    int tid = threadIdx.x;
    int tx = tid & 15, ty = tid >> 4;
    float acc[8][8];
#pragma unroll
    for (int i = 0; i < 8; i++)
#pragma unroll
        for (int j = 0; j < 8; j++) acc[i][j] = 0.f;

    for (int kb = 0; kb < CC/16; kb++) {
        // A tile: [k][m], rows contiguous in m -> direct float4 copy
#pragma unroll
        for (int r = 0; r < 2; r++) {
            int p = tid + 256*r;
            int k = p >> 5, mq = p & 31;
            float4 v = *(const float4*)(A + (size_t)(kb*16 + k)*NN + mBase + mq*4);
            *(float4*)(As + k*128 + mq*4) = v;
        }
        // B tile: Bs[k][n] = w1[n*259 + 3 + kb*16 + k]
#pragma unroll
        for (int r = 0; r < 8; r++) {
            int p = tid + 256*r;
            int k = p >> 7, n = p & 127;
            Bs[k*128 + n] = w1[n*(CC+3) + 3 + kb*16 + k];
        }
        __syncthreads();
#pragma unroll
        for (int k = 0; k < 16; k++) {
            float4 a0 = *(const float4*)(As + k*128 + ty*8);
            float4 a1 = *(const float4*)(As + k*128 + ty*8 + 4);
            float4 b0 = *(const float4*)(Bs + k*128 + tx*8);
            float4 b1 = *(const float4*)(Bs + k*128 + tx*8 + 4);
            float am[8] = {a0.x,a0.y,a0.z,a0.w,a1.x,a1.y,a1.z,a1.w};
            float bn[8] = {b0.x,b0.y,b0.z,b0.w,b1.x,b1.y,b1.z,b1.w};
#pragma unroll
            for (int i = 0; i < 8; i++)
#pragma unroll
                for (int j = 0; j < 8; j++) acc[i][j] += am[i]*bn[j];
        }
        __syncthreads();
    }
#pragma unroll
    for (int i = 0; i < 8; i++) {
        float4 v0 = make_float4(acc[i][0], acc[i][1], acc[i][2], acc[i][3]);
        float4 v1 = make_float4(acc[i][4], acc[i][5], acc[i][6], acc[i][7]);
        *(float4*)(C + (size_t)(ty*8 + i)*HIDC + tx*8)     = v0;
        *(float4*)(C + (size_t)(ty*8 + i)*HIDC + tx*8 + 4) = v1;
    }
}

// ---------------------------------------------------------------------------
// Assemble conv1: Y1[pix][o] = PF[b, idx[pix]][o] + W1xyz[o] . gxyz[pix]
// + accumulate layer-0 BN stats.
__global__ __launch_bounds__(256) void assemble_kernel(const float* __restrict__ w1)
{
    __shared__ float s_wx[HIDC], s_wy[HIDC], s_wz[HIDC];
    __shared__ float s_sum[HIDC], s_sq[HIDC];
    int tid = threadIdx.x, lane = tid & 31, w = tid >> 5;
    if (tid < HIDC) {
        s_wx[tid] = w1[tid*(CC+3) + 0];
        s_wy[tid] = w1[tid*(CC+3) + 1];
        s_wz[tid] = w1[tid*(CC+3) + 2];
        s_sum[tid] = 0.f; s_sq[tid] = 0.f;
    }
    __syncthreads();

    float ls[4] = {0,0,0,0}, lq[4] = {0,0,0,0};
    float wx[4], wy[4], wz[4];
#pragma unroll
    for (int j = 0; j < 4; j++) {
        int o = lane*4 + j;
        wx[j] = s_wx[o]; wy[j] = s_wy[o]; wz[j] = s_wz[o];
    }
    for (int i = 0; i < 16; i++) {
        int p = blockIdx.x*128 + w*16 + i;
        int b = p >> 13;
        int n = g_idx[p];
        float gx = g_gxyz[(size_t)p*3+0];
        float gy = g_gxyz[(size_t)p*3+1];
        float gz = g_gxyz[(size_t)p*3+2];
        float4 v = *(const float4*)(g_PF + ((size_t)b*NN + n)*HIDC + lane*4);
        float y[4] = {v.x, v.y, v.z, v.w};
        float4 o4;
#pragma unroll
        for (int j = 0; j < 4; j++) {
            float r = y[j] + wx[j]*gx + wy[j]*gy + wz[j]*gz;
            y[j] = r;
            ls[j] += r; lq[j] += r*r;
        }
        o4 = make_float4(y[0], y[1], y[2], y[3]);
        *(float4*)(g_Y1 + (size_t)p*HIDC + lane*4) = o4;
    }
#pragma unroll
    for (int j = 0; j < 4; j++) {
        atomicAdd(&s_sum[lane*4 + j], ls[j]);
        atomicAdd(&s_sq [lane*4 + j], lq[j]);
    }
    __syncthreads();
    if (tid < HIDC)      atomicAdd(&g_stats[0*256 + tid], (double)s_sum[tid]);
    else if (tid < 256)  atomicAdd(&g_stats[0*256 + 128 + (tid-128)], (double)s_sq[tid-128]);
}

// ---------------------------------------------------------------------------
__global__ void finalize_bn_kernel(int L, const float* __restrict__ g,
                                   const float* __restrict__ be)
{
    int c = threadIdx.x;
    if (c >= HIDC) return;
    const double cnt = (double)NPIX;
    double s = g_stats[L*256 + c];
    double q = g_stats[L*256 + 128 + c];
    double m = s / cnt;
    double v = q / cnt - m*m;
    if (v < 0.0) v = 0.0;
    float scale = g[c] / sqrtf((float)v + 1e-5f);
    g_bn[L*384 + c]       = (float)m;
    g_bn[L*384 + 128 + c] = scale;
    g_bn[L*384 + 256 + c] = be[c];
}

// ---------------------------------------------------------------------------
// NT GEMM for layers 2/3: C[m,o] = sum_k relu(bn_prev(A[m,k])) * W[o,k]
// M=262144, N=128, K=128; BM=BN=128, BK=16; fused next-layer stats.
__global__ __launch_bounds__(256) void gemm_nt_kernel(const float* __restrict__ W, int layer)
{
    __shared__ float As[16*132];
    __shared__ float Bs[16*132];
    __shared__ float s_sum[HIDC], s_sq[HIDC];
    const float* A  = (layer == 1) ? g_Y1 : g_Y2;
    float*       Y  = (layer == 1) ? g_Y2 : g_Y1;
    const float* bn = g_bn + (layer-1)*384;
    int statL = layer;

    int tid = threadIdx.x;
    if (tid < HIDC) { s_sum[tid] = 0.f; s_sq[tid] = 0.f; }
    size_t mBase = (size_t)blockIdx.x * 128;
    int tx = tid & 15, ty = tid >> 4;
    float acc[8][8];
#pragma unroll
    for (int i = 0; i < 8; i++)
#pragma unroll
        for (int j = 0; j < 8; j++) acc[i][j] = 0.f;

    for (int kb = 0; kb < 8; kb++) {
#pragma unroll
        for (int r = 0; r < 2; r++) {
            int p = tid + 256*r;
            int row = p >> 2, qd = p & 3;
            int c = kb*16 + qd*4;
            // A with prev-layer BN+ReLU folded in
            float4 v = *(const float4*)(A + (mBase + row)*HIDC + c);
            As[(qd*4+0)*132 + row] = fmaxf(0.f, (v.x - bn[c+0])*bn[128+c+0] + bn[256+c+0]);
            As[(qd*4+1)*132 + row] = fmaxf(0.f, (v.y - bn[c+1])*bn[128+c+1] + bn[256+c+1]);
            As[(qd*4+2)*132 + row] = fmaxf(0.f, (v.z - bn[c+2])*bn[128+c+2] + bn[256+c+2]);
            As[(qd*4+3)*132 + row] = fmaxf(0.f, (v.w - bn[c+3])*bn[128+c+3] + bn[256+c+3]);
            // B (weights, row-major [o][k])
            float4 wv = *(const float4*)(W + (size_t)row*HIDC + c);
            Bs[(qd*4+0)*132 + row] = wv.x;
            Bs[(qd*4+1)*132 + row] = wv.y;
            Bs[(qd*4+2)*132 + row] = wv.z;
            Bs[(qd*4+3)*132 + row] = wv.w;
        }
        __syncthreads();
#pragma unroll
        for (int k = 0; k < 16; k++) {
            float4 a0 = *(const float4*)(As + k*132 + ty*8);
            float4 a1 = *(const float4*)(As + k*132 + ty*8 + 4);
            float4 b0 = *(const float4*)(Bs + k*132 + tx*8);
            float4 b1 = *(const float4*)(Bs + k*132 + tx*8 + 4);
            float am[8] = {a0.x,a0.y,a0.z,a0.w,a1.x,a1.y,a1.z,a1.w};
            float bnr[8] = {b0.x,b0.y,b0.z,b0.w,b1.x,b1.y,b1.z,b1.w};
#pragma unroll
            for (int i = 0; i < 8; i++)
#pragma unroll
                for (int j = 0; j < 8; j++) acc[i][j] += am[i]*bnr[j];
        }
        __syncthreads();
    }
    // write + per-channel stats
#pragma unroll
    for (int i = 0; i < 8; i++) {
        float4 v0 = make_float4(acc[i][0], acc[i][1], acc[i][2], acc[i][3]);
        float4 v1 = make_float4(acc[i][4], acc[i][5], acc[i][6], acc[i][7]);
        *(float4*)(Y + (mBase + ty*8 + i)*HIDC + tx*8)     = v0;
        *(float4*)(Y + (mBase + ty*8 + i)*HIDC + tx*8 + 4) = v1;
    }
#pragma unroll
    for (int j = 0; j < 8; j++) {
        float s = 0.f, q = 0.f;
#pragma unroll
        for (int i = 0; i < 8; i++) { float v = acc[i][j]; s += v; q += v*v; }
        atomicAdd(&s_sum[tx*8 + j], s);
        atomicAdd(&s_sq [tx*8 + j], q);
    }
    __syncthreads();
    if (tid < HIDC)      atomicAdd(&g_stats[statL*256 + tid], (double)s_sum[tid]);
    else if (tid < 256)  atomicAdd(&g_stats[statL*256 + 128 + (tid-128)], (double)s_sq[tid-128]);
}

// ---------------------------------------------------------------------------
// Maxpool over NS with BN3+ReLU folded in (relu(max(bn(y))) == max(relu(bn(y)))).
// smem transpose for coalesced channel-major output writes.
__global__ __launch_bounds__(256) void maxpool_kernel(float* __restrict__ out)
{
    __shared__ float T[HIDC][33];
    int b  = blockIdx.x >> 4;
    int pb = blockIdx.x & 15;
    int tid = threadIdx.x, lane = tid & 31, w = tid >> 5;
    const float* bn = g_bn + 2*384;
    float mean[4], sc[4], bt[4];
#pragma unroll
    for (int j = 0; j < 4; j++) {
        int o = lane*4 + j;
        mean[j] = bn[o]; sc[j] = bn[128+o]; bt[j] = bn[256+o];
    }
    for (int pi = 0; pi < 4; pi++) {
        int p = pb*32 + w*4 + pi;
        size_t base = ((size_t)(b*NPQ + p) * NSAMP) * HIDC;
        float mx[4] = {-3.4e38f, -3.4e38f, -3.4e38f, -3.4e38f};
#pragma unroll
        for (int s = 0; s < NSAMP; s++) {
            float4 v = *(const float4*)(g_Y1 + base + (size_t)s*HIDC + lane*4);
            mx[0] = fmaxf(mx[0], v.x);
            mx[1] = fmaxf(mx[1], v.y);
            mx[2] = fmaxf(mx[2], v.z);
            mx[3] = fmaxf(mx[3], v.w);
        }
#pragma unroll
        for (int j = 0; j < 4; j++)
            T[lane*4 + j][w*4 + pi] = fmaxf(0.f, (mx[j] - mean[j])*sc[j] + bt[j]);
    }
    __syncthreads();
#pragma unroll
    for (int r = 0; r < 16; r++) {
        int flat = tid + 256*r;
        int o = flat >> 5, pl = flat & 31;
        out[OUT_FEAT + (size_t)b*(HIDC*NPQ) + (size_t)o*NPQ + pb*32 + pl] = T[o][pl];
    }
}

// ---------------------------------------------------------------------------
extern "C" void kernel_launch(void* const* d_in, const int* in_sizes, int n_in,
                              void* d_out, int out_size)
{
    const float* xyz  = (const float*)d_in[0];
    const float* feat = (const float*)d_in[1];
    const float* seed = (const float*)d_in[2];
    const float* w1   = (const float*)d_in[3];
    const float* g1   = (const float*)d_in[4];
    const float* be1  = (const float*)d_in[5];
    const float* w2   = (const float*)d_in[6];
    const float* g2   = (const float*)d_in[7];
    const float* be2  = (const float*)d_in[8];
    const float* w3   = (const float*)d_in[9];
    const float* g3   = (const float*)d_in[10];
    const float* be3  = (const float*)d_in[11];
    float* out = (float*)d_out;

    zero_stats_kernel<<<3, 256>>>();
    fps_kernel<<<BB, 1024>>>(seed, xyz, out);
    bq_kernel<<<(BB*NPQ)/8, 256>>>(xyz, out);
    gemm1_kernel<<<dim3(NN/128, 1, BB), 256>>>(feat, w1);
    assemble_kernel<<<NPIX/128, 256>>>(w1);
    finalize_bn_kernel<<<1, 128>>>(0, g1, be1);
    gemm_nt_kernel<<<NPIX/128, 256>>>(w2, 1);
    finalize_bn_kernel<<<1, 128>>>(1, g2, be2);
    gemm_nt_kernel<<<NPIX/128, 256>>>(w3, 2);
    finalize_bn_kernel<<<1, 128>>>(2, g3, be3);
    maxpool_kernel<<<BB*16, 256>>>(out);
}

// round 3
// speedup vs baseline: 1.1563x; 1.1563x over previous
#include <cuda_runtime.h>
#include <math.h>
#include <stdint.h>

#define BB    32
#define NN    4096
#define NPQ   512
#define NSAMP 16
#define CC    256
#define HIDC  128
#define NPIX  (BB*NPQ*NSAMP)   /* 262144 */
#define NPTS  (BB*NN)          /* 131072 */

#define OUT_XYZ  0
#define OUT_FEAT (BB*NPQ*3)                  /* 49152 */
#define OUT_INDS (OUT_FEAT + BB*HIDC*NPQ)    /* 2146304 */

// ------------- static scratch (no allocations) -------------
__device__ float  g_PF[(size_t)NPTS*HIDC];    // per-point conv1 feature part
__device__ float  g_Y1[(size_t)NPIX*HIDC];    // activations ping
__device__ float  g_Y2[(size_t)NPIX*HIDC];    // activations pong
__device__ int    g_idx[NPIX];
__device__ float  g_gxyz[(size_t)NPIX*3];
__device__ double g_stats[3*2*HIDC];
__device__ float  g_bn[3*3*HIDC];
__device__ float  g_W1f[HIDC*CC];             // packed W1 feature part [o][k]

#define MMA8(c, a, b) asm volatile( \
  "mma.sync.aligned.m16n8k8.row.col.f32.tf32.tf32.f32 " \
  "{%0,%1,%2,%3}, {%4,%5,%6,%7}, {%8,%9}, {%0,%1,%2,%3};" \
  : "+f"((c)[0]), "+f"((c)[1]), "+f"((c)[2]), "+f"((c)[3]) \
  : "r"((a)[0]), "r"((a)[1]), "r"((a)[2]), "r"((a)[3]), "r"((b)[0]), "r"((b)[1]))

// ---------------------------------------------------------------------------
__global__ void zero_stats_kernel() {
    int i = blockIdx.x*256 + threadIdx.x;
    if (i < 3*2*HIDC) g_stats[i] = 0.0;
}

__global__ void prep_w1_kernel(const float* __restrict__ w1) {
    int o = blockIdx.x, k = threadIdx.x;
    g_W1f[o*CC + k] = w1[o*(CC+3) + 3 + k];
}

// ---------------------------------------------------------------------------
// FPS: one block per batch, 1024 threads, 4 points each. ONE barrier/iter.
// Bit-exact distance: ((dx*dx + dy*dy) + dz*dz) with rn ops (no FMA).
__global__ __launch_bounds__(1024) void fps_kernel(
    const float* __restrict__ seed, const float* __restrict__ xyz,
    float* __restrict__ out)
{
    int b = blockIdx.x;
    int t = threadIdx.x;
    int lane = t & 31, wid = t >> 5;
    __shared__ float s_cv[2][32], s_cx[2][32], s_cy[2][32], s_cz[2][32];
    __shared__ int   s_ci[2][32];
    __shared__ int   s_inds[NPQ];

    const float* sb = seed + (size_t)b*NN*3;
    float px[4], py[4], pz[4], dist[4];
#pragma unroll
    for (int j = 0; j < 4; j++) {
        int i = t + j*1024;
        px[j] = sb[i*3+0];
        py[j] = sb[i*3+1];
        pz[j] = sb[i*3+2];
        dist[j] = 1e10f;
    }
    if (t == 0) s_inds[0] = 0;
    // coordinates of point 0 (broadcast load)
    float lx = sb[0], ly = sb[1], lz = sb[2];

    for (int it = 1; it < NPQ; ++it) {
        float bv = -1.0f; int bi = 0;
        float bx = 0.f, by = 0.f, bz = 0.f;
#pragma unroll
        for (int j = 0; j < 4; j++) {
            float dx = __fadd_rn(px[j], -lx);
            float dy = __fadd_rn(py[j], -ly);
            float dz = __fadd_rn(pz[j], -lz);
            float d  = __fadd_rn(__fadd_rn(__fmul_rn(dx,dx), __fmul_rn(dy,dy)),
                                 __fmul_rn(dz,dz));
            dist[j] = fminf(dist[j], d);
            if (dist[j] > bv) { bv = dist[j]; bi = t + j*1024;
                                bx = px[j]; by = py[j]; bz = pz[j]; }
        }
        // warp butterfly reduce: max value, smallest index on ties, carry coords
#pragma unroll
        for (int off = 16; off > 0; off >>= 1) {
            float ov = __shfl_xor_sync(0xffffffffu, bv, off);
            int   oi = __shfl_xor_sync(0xffffffffu, bi, off);
            float ox = __shfl_xor_sync(0xffffffffu, bx, off);
            float oy = __shfl_xor_sync(0xffffffffu, by, off);
            float oz = __shfl_xor_sync(0xffffffffu, bz, off);
            if (ov > bv || (ov == bv && oi < bi)) {
                bv = ov; bi = oi; bx = ox; by = oy; bz = oz;
            }
        }
        int buf = it & 1;
        if (lane == 0) {
            s_cv[buf][wid] = bv; s_ci[buf][wid] = bi;
            s_cx[buf][wid] = bx; s_cy[buf][wid] = by; s_cz[buf][wid] = bz;
        }
        __syncthreads();
        // every warp redundantly reduces the 32 candidates (no 2nd barrier;
        // parity double-buffering protects slots across iterations)
        float v  = s_cv[buf][lane];
        int   ci = s_ci[buf][lane];
        int   sl = lane;
#pragma unroll
        for (int off = 16; off > 0; off >>= 1) {
            float ov = __shfl_xor_sync(0xffffffffu, v,  off);
            int   oi = __shfl_xor_sync(0xffffffffu, ci, off);
            int   os = __shfl_xor_sync(0xffffffffu, sl, off);
            if (ov > v || (ov == v && oi < ci)) { v = ov; ci = oi; sl = os; }
        }
        lx = s_cx[buf][sl]; ly = s_cy[buf][sl]; lz = s_cz[buf][sl];
        if (t == 0) s_inds[it] = ci;
    }
    __syncthreads();

    for (int i = t; i < NPQ; i += 1024) {
        int id = s_inds[i];
        out[OUT_INDS + b*NPQ + i] = (float)id;
        const float* xb = xyz + ((size_t)b*NN + id)*3;
        out[((size_t)b*NPQ + i)*3 + 0] = xb[0];
        out[((size_t)b*NPQ + i)*3 + 1] = xb[1];
        out[((size_t)b*NPQ + i)*3 + 2] = xb[2];
    }
}

// ---------------------------------------------------------------------------
// Ball query: one warp per query. First-16-in-index-order semantics via ballot.
__global__ __launch_bounds__(256) void bq_kernel(
    const float* __restrict__ xyz, const float* __restrict__ out)
{
    int q = blockIdx.x*8 + (threadIdx.x >> 5);
    int lane = threadIdx.x & 31;
    int b = q >> 9;
    const float R2c = (float)(0.3*0.3);
    const float RAD = 0.3f;

    float qx = out[(size_t)q*3+0];
    float qy = out[(size_t)q*3+1];
    float qz = out[(size_t)q*3+2];
    const float* xb = xyz + (size_t)b*NN*3;

    int found = 0, firstIdx = -1;
    for (int s = 0; s < NN/32 && found < NSAMP; ++s) {
        int i = s*32 + lane;
        float x = xb[i*3+0], y = xb[i*3+1], z = xb[i*3+2];
        float dx = __fadd_rn(qx, -x);
        float dy = __fadd_rn(qy, -y);
        float dz = __fadd_rn(qz, -z);
        float d  = __fadd_rn(__fadd_rn(__fmul_rn(dx,dx), __fmul_rn(dy,dy)),
                             __fmul_rn(dz,dz));
        bool pred = d < R2c;
        unsigned mask = __ballot_sync(0xffffffffu, pred);
        if (firstIdx < 0 && mask) firstIdx = s*32 + __ffs(mask) - 1;
        if (pred) {
            int rank = __popc(mask & ((1u << lane) - 1u));
            int pos = found + rank;
            if (pos < NSAMP) {
                g_idx[q*NSAMP + pos] = i;
                g_gxyz[((size_t)q*NSAMP + pos)*3 + 0] = __fdiv_rn(__fadd_rn(x, -qx), RAD);
                g_gxyz[((size_t)q*NSAMP + pos)*3 + 1] = __fdiv_rn(__fadd_rn(y, -qy), RAD);
                g_gxyz[((size_t)q*NSAMP + pos)*3 + 2] = __fdiv_rn(__fadd_rn(z, -qz), RAD);
            }
        }
        found += __popc(mask);
    }
    if (found < NSAMP) {
        float fx = xb[firstIdx*3+0], fy = xb[firstIdx*3+1], fz = xb[firstIdx*3+2];
        float p0 = __fdiv_rn(__fadd_rn(fx, -qx), RAD);
        float p1 = __fdiv_rn(__fadd_rn(fy, -qy), RAD);
        float p2 = __fdiv_rn(__fadd_rn(fz, -qz), RAD);
        if (lane >= found && lane < NSAMP) {
            g_idx[q*NSAMP + lane] = firstIdx;
            g_gxyz[((size_t)q*NSAMP + lane)*3 + 0] = p0;
            g_gxyz[((size_t)q*NSAMP + lane)*3 + 1] = p1;
            g_gxyz[((size_t)q*NSAMP + lane)*3 + 2] = p2;
        }
    }
}

// ---------------------------------------------------------------------------
// GEMM1 (tf32 tensor cores): PF[b,m,o] = sum_c feat[b,c,m] * W1f[o,c]
// per batch M=4096, N=128, K=256. Block: 128x128x32, 8 warps (2x4), warp 64x32.
__global__ __launch_bounds__(256) void gemm1_tc(const float* __restrict__ feat)
{
    __shared__ float As[32*132];   // [k][m], stride 132
    __shared__ float Bs[128*36];   // [n][k], stride 36
    int b = blockIdx.z;
    int mBase = blockIdx.x*128;
    const float* A = feat + (size_t)b*CC*NN;
    float* C = g_PF + ((size_t)b*NN + mBase)*HIDC;
    int tid = threadIdx.x;
    int lane = tid & 31, wid = tid >> 5;
    int wm = wid >> 2, wn = wid & 3;     // 2 x 4 warp grid
    int lq = lane >> 2, lr = lane & 3;

    float c[4][4][4];
#pragma unroll
    for (int i = 0; i < 4; i++)
#pragma unroll
        for (int j = 0; j < 4; j++)
#pragma unroll
            for (int r = 0; r < 4; r++) c[i][j][r] = 0.f;

    for (int kb = 0; kb < CC/32; kb++) {
        // A tile: coalesced along m, direct [k][m] store
#pragma unroll
        for (int r = 0; r < 4; r++) {
            int p = tid + 256*r;
            int k = p >> 5, mq = p & 31;
            float4 v = *(const float4*)(A + (size_t)(kb*32 + k)*NN + mBase + mq*4);
            *(float4*)(As + k*132 + mq*4) = v;
        }
        // B tile: W1f packed [n][256]
#pragma unroll
        for (int r = 0; r < 4; r++) {
            int p = tid + 256*r;
            int n = p >> 3, kq = p & 7;
            float4 v = *(const float4*)(g_W1f + n*CC + kb*32 + kq*4);
            *(float4*)(Bs + n*36 + kq*4) = v;
        }
        __syncthreads();
#pragma unroll
        for (int ks = 0; ks < 4; ks++) {
            int k0 = ks*8;
            uint32_t af[4][4], bf[4][2];
#pragma unroll
            for (int mi = 0; mi < 4; mi++) {
                int m0 = wm*64 + mi*16;
                af[mi][0] = __float_as_uint(As[(k0+lr  )*132 + m0 + lq    ]);
                af[mi][1] = __float_as_uint(As[(k0+lr  )*132 + m0 + 8 + lq]);
                af[mi][2] = __float_as_uint(As[(k0+lr+4)*132 + m0 + lq    ]);
                af[mi][3] = __float_as_uint(As[(k0+lr+4)*132 + m0 + 8 + lq]);
            }
#pragma unroll
            for (int nj = 0; nj < 4; nj++) {
                int n0 = wn*32 + nj*8;
                bf[nj][0] = __float_as_uint(Bs[(n0+lq)*36 + k0 + lr    ]);
                bf[nj][1] = __float_as_uint(Bs[(n0+lq)*36 + k0 + lr + 4]);
            }
#pragma unroll
            for (int mi = 0; mi < 4; mi++)
#pragma unroll
                for (int nj = 0; nj < 4; nj++)
                    MMA8(c[mi][nj], af[mi], bf[nj]);
        }
        __syncthreads();
    }
#pragma unroll
    for (int mi = 0; mi < 4; mi++) {
#pragma unroll
        for (int nj = 0; nj < 4; nj++) {
            int gr  = wm*64 + mi*16 + lq;
            int col = wn*32 + nj*8 + 2*lr;
            float2 v0 = make_float2(c[mi][nj][0], c[mi][nj][1]);
            float2 v1 = make_float2(c[mi][nj][2], c[mi][nj][3]);
            *(float2*)(C + (size_t)gr*HIDC + col)     = v0;
            *(float2*)(C + (size_t)(gr+8)*HIDC + col) = v1;
        }
    }
}

// ---------------------------------------------------------------------------
// Assemble conv1: Y1 = PF[gathered] + W1xyz . gxyz  + layer-0 BN stats.
__global__ __launch_bounds__(256) void assemble_kernel(const float* __restrict__ w1)
{
    __shared__ float s_wx[HIDC], s_wy[HIDC], s_wz[HIDC];
    __shared__ float s_sum[HIDC], s_sq[HIDC];
    int tid = threadIdx.x, lane = tid & 31, w = tid >> 5;
    if (tid < HIDC) {
        s_wx[tid] = w1[tid*(CC+3) + 0];
        s_wy[tid] = w1[tid*(CC+3) + 1];
        s_wz[tid] = w1[tid*(CC+3) + 2];
        s_sum[tid] = 0.f; s_sq[tid] = 0.f;
    }
    __syncthreads();

    float ls[4] = {0,0,0,0}, lqa[4] = {0,0,0,0};
    float wx[4], wy[4], wz[4];
#pragma unroll
    for (int j = 0; j < 4; j++) {
        int o = lane*4 + j;
        wx[j] = s_wx[o]; wy[j] = s_wy[o]; wz[j] = s_wz[o];
    }
    for (int i = 0; i < 16; i++) {
        int p = blockIdx.x*128 + w*16 + i;
        int b = p >> 13;
        int n = g_idx[p];
        float gx = g_gxyz[(size_t)p*3+0];
        float gy = g_gxyz[(size_t)p*3+1];
        float gz = g_gxyz[(size_t)p*3+2];
        float4 v = *(const float4*)(g_PF + ((size_t)b*NN + n)*HIDC + lane*4);
        float y[4] = {v.x, v.y, v.z, v.w};
#pragma unroll
        for (int j = 0; j < 4; j++) {
            float r = y[j] + wx[j]*gx + wy[j]*gy + wz[j]*gz;
            y[j] = r;
            ls[j] += r; lqa[j] += r*r;
        }
        *(float4*)(g_Y1 + (size_t)p*HIDC + lane*4) = make_float4(y[0],y[1],y[2],y[3]);
    }
#pragma unroll
    for (int j = 0; j < 4; j++) {
        atomicAdd(&s_sum[lane*4 + j], ls[j]);
        atomicAdd(&s_sq [lane*4 + j], lqa[j]);
    }
    __syncthreads();
    if (tid < HIDC)      atomicAdd(&g_stats[0*256 + tid], (double)s_sum[tid]);
    else if (tid < 256)  atomicAdd(&g_stats[0*256 + 128 + (tid-128)], (double)s_sq[tid-128]);
}

// ---------------------------------------------------------------------------
__global__ void finalize_bn_kernel(int L, const float* __restrict__ g,
                                   const float* __restrict__ be)
{
    int cc = threadIdx.x;
    if (cc >= HIDC) return;
    const double cnt = (double)NPIX;
    double s = g_stats[L*256 + cc];
    double q = g_stats[L*256 + 128 + cc];
    double m = s / cnt;
    double v = q / cnt - m*m;
    if (v < 0.0) v = 0.0;
    float scale = g[cc] / sqrtf((float)v + 1e-5f);
    g_bn[L*384 + cc]       = (float)m;
    g_bn[L*384 + 128 + cc] = scale;
    g_bn[L*384 + 256 + cc] = be[cc];
}

// ---------------------------------------------------------------------------
// NT GEMM (tf32): C[m,o] = sum_k relu(bn_prev(A[m,k])) * W[o,k]
// M=262144, N=128, K=128. Fused next-layer BN stats in epilogue.
__global__ __launch_bounds__(256) void gemm_nt_tc(const float* __restrict__ W, int layer)
{
    __shared__ float As[128*36];   // [m][k] stride 36
    __shared__ float Bs[128*36];   // [n][k] stride 36
    __shared__ float s_bnp[384];
    __shared__ float s_sum[HIDC], s_sq[HIDC];
    const float* A  = (layer == 1) ? g_Y1 : g_Y2;
    float*       Y  = (layer == 1) ? g_Y2 : g_Y1;
    const float* bnp = g_bn + (layer-1)*384;

    int tid = threadIdx.x;
    int lane = tid & 31, wid = tid >> 5;
    int wm = wid >> 2, wn = wid & 3;
    int lq = lane >> 2, lr = lane & 3;
    if (tid < HIDC) { s_sum[tid] = 0.f; s_sq[tid] = 0.f; }
    for (int i = tid; i < 384; i += 256) s_bnp[i] = bnp[i];
    __syncthreads();

    size_t mBase = (size_t)blockIdx.x * 128;
    float c[4][4][4];
#pragma unroll
    for (int i = 0; i < 4; i++)
#pragma unroll
        for (int j = 0; j < 4; j++)
#pragma unroll
            for (int r = 0; r < 4; r++) c[i][j][r] = 0.f;

    for (int kb = 0; kb < 4; kb++) {
#pragma unroll
        for (int r = 0; r < 4; r++) {
            int p = tid + 256*r;
            int row = p >> 3, kq = p & 7;
            int ch = kb*32 + kq*4;
            float4 v = *(const float4*)(A + (mBase + row)*HIDC + ch);
            float4 o4;
            o4.x = fmaxf(0.f, (v.x - s_bnp[ch+0])*s_bnp[128+ch+0] + s_bnp[256+ch+0]);
            o4.y = fmaxf(0.f, (v.y - s_bnp[ch+1])*s_bnp[128+ch+1] + s_bnp[256+ch+1]);
            o4.z = fmaxf(0.f, (v.z - s_bnp[ch+2])*s_bnp[128+ch+2] + s_bnp[256+ch+2]);
            o4.w = fmaxf(0.f, (v.w - s_bnp[ch+3])*s_bnp[128+ch+3] + s_bnp[256+ch+3]);
            *(float4*)(As + row*36 + kq*4) = o4;
            float4 wv = *(const float4*)(W + (size_t)row*HIDC + ch);
            *(float4*)(Bs + row*36 + kq*4) = wv;
        }
        __syncthreads();
#pragma unroll
        for (int ks = 0; ks < 4; ks++) {
            int k0 = ks*8;
            uint32_t af[4][4], bf[4][2];
#pragma unroll
            for (int mi = 0; mi < 4; mi++) {
                int m0 = wm*64 + mi*16;
                af[mi][0] = __float_as_uint(As[(m0 + lq    )*36 + k0 + lr    ]);
                af[mi][1] = __float_as_uint(As[(m0 + 8 + lq)*36 + k0 + lr    ]);
                af[mi][2] = __float_as_uint(As[(m0 + lq    )*36 + k0 + lr + 4]);
                af[mi][3] = __float_as_uint(As[(m0 + 8 + lq)*36 + k0 + lr + 4]);
            }
#pragma unroll
            for (int nj = 0; nj < 4; nj++) {
                int n0 = wn*32 + nj*8;
                bf[nj][0] = __float_as_uint(Bs[(n0+lq)*36 + k0 + lr    ]);
                bf[nj][1] = __float_as_uint(Bs[(n0+lq)*36 + k0 + lr + 4]);
            }
#pragma unroll
            for (int mi = 0; mi < 4; mi++)
#pragma unroll
                for (int nj = 0; nj < 4; nj++)
                    MMA8(c[mi][nj], af[mi], bf[nj]);
        }
        __syncthreads();
    }
    // write + per-channel stats
#pragma unroll
    for (int mi = 0; mi < 4; mi++) {
#pragma unroll
        for (int nj = 0; nj < 4; nj++) {
            size_t gr = mBase + wm*64 + mi*16 + lq;
            int col = wn*32 + nj*8 + 2*lr;
            *(float2*)(Y + gr*HIDC + col)     = make_float2(c[mi][nj][0], c[mi][nj][1]);
            *(float2*)(Y + (gr+8)*HIDC + col) = make_float2(c[mi][nj][2], c[mi][nj][3]);
        }
    }
#pragma unroll
    for (int nj = 0; nj < 4; nj++) {
        int ch = wn*32 + nj*8 + 2*lr;
        float s0 = 0.f, q0 = 0.f, s1 = 0.f, q1 = 0.f;
#pragma unroll
        for (int mi = 0; mi < 4; mi++) {
            float x;
            x = c[mi][nj][0]; s0 += x; q0 += x*x;
            x = c[mi][nj][2]; s0 += x; q0 += x*x;
            x = c[mi][nj][1]; s1 += x; q1 += x*x;
            x = c[mi][nj][3]; s1 += x; q1 += x*x;
        }
        atomicAdd(&s_sum[ch],   s0); atomicAdd(&s_sq[ch],   q0);
        atomicAdd(&s_sum[ch+1], s1); atomicAdd(&s_sq[ch+1], q1);
    }
    __syncthreads();
    if (tid < HIDC)      atomicAdd(&g_stats[layer*256 + tid], (double)s_sum[tid]);
    else if (tid < 256)  atomicAdd(&g_stats[layer*256 + 128 + (tid-128)], (double)s_sq[tid-128]);
}

// ---------------------------------------------------------------------------
// Maxpool over NS with BN3+ReLU folded in; smem transpose for coalesced writes.
__global__ __launch_bounds__(256) void maxpool_kernel(float* __restrict__ out)
{
    __shared__ float T[HIDC][33];
    int b  = blockIdx.x >> 4;
    int pb = blockIdx.x & 15;
    int tid = threadIdx.x, lane = tid & 31, w = tid >> 5;
    const float* bnp = g_bn + 2*384;
    float mean[4], sc[4], bt[4];
#pragma unroll
    for (int j = 0; j < 4; j++) {
        int o = lane*4 + j;
        mean[j] = bnp[o]; sc[j] = bnp[128+o]; bt[j] = bnp[256+o];
    }
    for (int pi = 0; pi < 4; pi++) {
        int p = pb*32 + w*4 + pi;
        size_t base = ((size_t)(b*NPQ + p) * NSAMP) * HIDC;
        float mx[4] = {-3.4e38f, -3.4e38f, -3.4e38f, -3.4e38f};
#pragma unroll
        for (int s = 0; s < NSAMP; s++) {
            float4 v = *(const float4*)(g_Y1 + base + (size_t)s*HIDC + lane*4);
            mx[0] = fmaxf(mx[0], v.x);
            mx[1] = fmaxf(mx[1], v.y);
            mx[2] = fmaxf(mx[2], v.z);
            mx[3] = fmaxf(mx[3], v.w);
        }
#pragma unroll
        for (int j = 0; j < 4; j++)
            T[lane*4 + j][w*4 + pi] = fmaxf(0.f, (mx[j] - mean[j])*sc[j] + bt[j]);
    }
    __syncthreads();
#pragma unroll
    for (int r = 0; r < 16; r++) {
        int flat = tid + 256*r;
        int o = flat >> 5, pl = flat & 31;
        out[OUT_FEAT + (size_t)b*(HIDC*NPQ) + (size_t)o*NPQ + pb*32 + pl] = T[o][pl];
    }
}

// ---------------------------------------------------------------------------
extern "C" void kernel_launch(void* const* d_in, const int* in_sizes, int n_in,
                              void* d_out, int out_size)
{
    const float* xyz  = (const float*)d_in[0];
    const float* feat = (const float*)d_in[1];
    const float* seed = (const float*)d_in[2];
    const float* w1   = (const float*)d_in[3];
    const float* g1   = (const float*)d_in[4];
    const float* be1  = (const float*)d_in[5];
    const float* w2   = (const float*)d_in[6];
    const float* g2   = (const float*)d_in[7];
    const float* be2  = (const float*)d_in[8];
    const float* w3   = (const float*)d_in[9];
    const float* g3   = (const float*)d_in[10];
    const float* be3  = (const float*)d_in[11];
    float* out = (float*)d_out;

    zero_stats_kernel<<<3, 256>>>();
    prep_w1_kernel<<<HIDC, CC>>>(w1);
    fps_kernel<<<BB, 1024>>>(seed, xyz, out);
    bq_kernel<<<(BB*NPQ)/8, 256>>>(xyz, out);
    gemm1_tc<<<dim3(NN/128, 1, BB), 256>>>(feat);
    assemble_kernel<<<NPIX/128, 256>>>(w1);
    finalize_bn_kernel<<<1, 128>>>(0, g1, be1);
    gemm_nt_tc<<<NPIX/128, 256>>>(w2, 1);
    finalize_bn_kernel<<<1, 128>>>(1, g2, be2);
    gemm_nt_tc<<<NPIX/128, 256>>>(w3, 2);
    finalize_bn_kernel<<<1, 128>>>(2, g3, be3);
    maxpool_kernel<<<BB*16, 256>>>(out);
}